// round 1
// baseline (speedup 1.0000x reference)
#include <cuda_runtime.h>

#define NSEG 128
#define KC   64
#define BZD  64

constexpr int PIX = 8;            // pixels (consecutive j) per thread
constexpr int THREADS = 128;
constexpr int ROWS_PER_BLOCK = THREADS * PIX / BZD;   // 16 rows
constexpr int TILES_PER_SEG = BZD / ROWS_PER_BLOCK;   // 4

__device__ __forceinline__ float ex2f(float x) {
    float r;
    asm("ex2.approx.ftz.f32 %0, %1;" : "=f"(r) : "f"(x));
    return r;
}

__global__ __launch_bounds__(THREADS)
void seg_splat_kernel(const float* __restrict__ u,
                      const float* __restrict__ a,
                      const float* __restrict__ B,
                      float* __restrict__ out)
{
    __shared__ float4 sP[KC];   // {A, Bc, C, a}  (log2e folded in)
    __shared__ float2 sU[KC];   // {u0, u1}

    const int n    = blockIdx.x / TILES_PER_SEG;
    const int tile = blockIdx.x % TILES_PER_SEG;
    const int tid  = threadIdx.x;

    // Precompute per-component quadratic-form coefficients (tril(B)^T tril(B))
    for (int k = tid; k < KC; k += THREADS) {
        const float* bp = B + (size_t)(n * KC + k) * 4;
        float b00 = bp[0];
        float b10 = bp[2];
        float b11 = bp[3];
        float q00 = b00 * b00 + b10 * b10;
        float q01 = b10 * b11;
        float q11 = b11 * b11;
        const float L = -0.72134752044448170368f;  // -0.5 * log2(e)
        sP[k] = make_float4(L * q00, 2.0f * L * q01, L * q11, a[n * KC + k]);
        const float* up = u + (size_t)(n * KC + k) * 2;
        sU[k] = make_float2(up[0], up[1]);
    }
    __syncthreads();

    constexpr int THREADS_PER_ROW = BZD / PIX;  // 8
    const int row = tid / THREADS_PER_ROW;
    const int j0  = (tid % THREADS_PER_ROW) * PIX;
    const int i   = tile * ROWS_PER_BLOCK + row;

    const float xi = ((float)i + 0.5f) * (1.0f / BZD);
    float yv[PIX];
#pragma unroll
    for (int jj = 0; jj < PIX; jj++)
        yv[jj] = ((float)(j0 + jj) + 0.5f) * (1.0f / BZD);

    float num[PIX], den[PIX];
#pragma unroll
    for (int jj = 0; jj < PIX; jj++) { num[jj] = 0.0f; den[jj] = 0.0f; }

#pragma unroll 4
    for (int k = 0; k < KC; k++) {
        float4 p  = sP[k];
        float2 uu = sU[k];
        float dx = xi - uu.x;
        float P1 = p.y * dx;           // B' * dx
        float P0 = (p.x * dx) * dx;    // A' * dx^2
#pragma unroll
        for (int jj = 0; jj < PIX; jj++) {
            float dy = yv[jj] - uu.y;
            float e  = fmaf(dy, fmaf(p.z, dy, P1), P0);  // A'dx^2 + B'dxdy + C'dy^2 (log2 scale)
            float kv = ex2f(e);
            den[jj] += kv;
            num[jj] = fmaf(p.w, kv, num[jj]);
        }
    }

    float* op = out + (size_t)n * (BZD * BZD) + (size_t)i * BZD + j0;
#pragma unroll
    for (int jj = 0; jj < PIX; jj++)
        op[jj] = num[jj] / fmaxf(den[jj], 1e-7f);
}

extern "C" void kernel_launch(void* const* d_in, const int* in_sizes, int n_in,
                              void* d_out, int out_size)
{
    const float* u = (const float*)d_in[0];
    const float* a = (const float*)d_in[1];
    const float* B = (const float*)d_in[2];
    float* out     = (float*)d_out;

    int blocks = NSEG * TILES_PER_SEG;  // 512
    seg_splat_kernel<<<blocks, THREADS>>>(u, a, B, out);
}